// round 15
// baseline (speedup 1.0000x reference)
#include <cuda_runtime.h>
#include <math.h>

#define NB   128
#define NHID 512
#define GATE_ELEMS (NB * NHID)   // 65536
#define NSPLIT 32
#define GEMM1_BLOCKS (8 * NSPLIT)  // 256, all co-resident at 2 CTAs/SM
#define EPI_BLOCKS 256             // gate-epilogue blocks at head of k_fused
#define G2_BLOCKS 16               // per pass; P and O run as parallel blocks
#define G2P_BASE EPI_BLOCKS        // 256
#define G2O_BASE (EPI_BLOCKS + G2_BLOCKS)      // 272
#define TRACE_BASE (EPI_BLOCKS + 2 * G2_BLOCKS) // 288
#define TRACE_BLOCKS 32768

// ---------------- device scratch (no allocations allowed) ----------------
__device__ float d_part[NSPLIT][NB * 1024];  // split-K partials, 16 MB
__device__ float d_av  [GATE_ELEMS];         // 1 - g
__device__ float d_cgv [GATE_ELEMS];         // dg * delta_h
__device__ float d_crv [GATE_ELEMS];         // dr * g
__device__ float d_hv  [GATE_ELEMS];         // new h
__device__ float d_pfull[GATE_ELEMS];        // tanh(p_pre), written by P-blocks
__device__ int   d_cnt [EPI_BLOCKS];         // per-block open counts
__device__ int   d_done;                     // epilogue counter (reset by k_gemm1)
__device__ int   d_pdone[G2_BLOCKS];         // P-tile flags (self-reset by O-blocks)

__device__ __forceinline__ void wait_done(int target)
{
    if (threadIdx.x == 0) {
        while (*(volatile int*)&d_done < target) __nanosleep(64);
        __threadfence();
    }
    __syncthreads();
}

// ---------------------------------------------------------------------------
// Launch 1: split-K dual GEMM for g/r pre-activation PARTIALS only.
//   CTA tile 128m x 128n, BK=16, 8x8 register tile, double-buffered.
//   grid = (8 n-tiles, 32 splits) = 256 CTAs, 2 resident/SM.
//   No barrier, no epilogue — k_fused's head blocks consume the partials
//   (kernel boundary orders partial stores before k_fused reads).
// ---------------------------------------------------------------------------
__global__ void __launch_bounds__(256, 2) k_gemm1(
    const float* __restrict__ x, const float* __restrict__ h_last,
    const float* __restrict__ w_gx, const float* __restrict__ w_gh,
    const float* __restrict__ w_rx, const float* __restrict__ w_rh)
{
    __shared__ float As[2][16 * 132];   // [stage][k][m(128)+pad]
    __shared__ float Ws[2][16 * 132];   // [stage][k][n(128)+pad]

    const int tid  = threadIdx.x;
    if (blockIdx.x == 0 && blockIdx.y == 0 && tid == 0)
        d_done = 0;                      // reset for this replay (ordered by kernel boundary)

    const int n0   = blockIdx.x * 128;   // n in [0,1024)
    const int s    = blockIdx.y;         // split 0..31
    const int half = s >> 4;             // 0: x-part, 1: h-part
    const int kb   = (s & 15) * 32;      // offset within the 512-wide half

    const bool g2 = (n0 >= 512);
    const int  j0 = g2 ? (n0 - 512) : n0;
    const float* A = half ? h_last : x;
    const float* W = g2 ? (half ? w_rh : w_rx) : (half ? w_gh : w_gx);
    float* outp    = d_part[s];

    const int lr = tid & 127;            // row (m for A, n for W)
    const int ka = (tid >> 7) << 3;      // k offset: 0 or 8 (two float4 each)

    const int tx = tid & 15;             // n-dir (8 cols)
    const int ty = tid >> 4;             // m-dir (8 rows)

    const float* Aload = A + lr * 512 + kb + ka;
    const float* Wload = W + (j0 + lr) * 512 + kb + ka;

    float acc[8][8];
    #pragma unroll
    for (int i = 0; i < 8; i++)
        #pragma unroll
        for (int j = 0; j < 8; j++) acc[i][j] = 0.f;

    float4 a0 = *(const float4*)(Aload);
    float4 a1 = *(const float4*)(Aload + 4);
    float4 w0 = *(const float4*)(Wload);
    float4 w1 = *(const float4*)(Wload + 4);

    {
        float* as = As[0]; float* ws = Ws[0];
        as[(ka+0)*132+lr]=a0.x; as[(ka+1)*132+lr]=a0.y; as[(ka+2)*132+lr]=a0.z; as[(ka+3)*132+lr]=a0.w;
        as[(ka+4)*132+lr]=a1.x; as[(ka+5)*132+lr]=a1.y; as[(ka+6)*132+lr]=a1.z; as[(ka+7)*132+lr]=a1.w;
        ws[(ka+0)*132+lr]=w0.x; ws[(ka+1)*132+lr]=w0.y; ws[(ka+2)*132+lr]=w0.z; ws[(ka+3)*132+lr]=w0.w;
        ws[(ka+4)*132+lr]=w1.x; ws[(ka+5)*132+lr]=w1.y; ws[(ka+6)*132+lr]=w1.z; ws[(ka+7)*132+lr]=w1.w;
    }
    __syncthreads();

    #pragma unroll 1
    for (int t = 0; t < 2; t++) {        // 2 k-tiles of 16 (k-chunk = 32)
        const int cur = t & 1;
        const float* as = As[cur];
        const float* ws = Ws[cur];

        if (t < 1) {                      // prefetch next k-tile
            a0 = *(const float4*)(Aload + 16);
            a1 = *(const float4*)(Aload + 20);
            w0 = *(const float4*)(Wload + 16);
            w1 = *(const float4*)(Wload + 20);
        }

        #pragma unroll
        for (int kk = 0; kk < 16; kk++) {
            float a[8], w[8];
            *(float4*)&a[0] = *(const float4*)(as + kk * 132 + (ty << 3));
            *(float4*)&a[4] = *(const float4*)(as + kk * 132 + (ty << 3) + 4);
            *(float4*)&w[0] = *(const float4*)(ws + kk * 132 + (tx << 3));
            *(float4*)&w[4] = *(const float4*)(ws + kk * 132 + (tx << 3) + 4);
            #pragma unroll
            for (int i = 0; i < 8; i++)
                #pragma unroll
                for (int j = 0; j < 8; j++)
                    acc[i][j] = fmaf(a[i], w[j], acc[i][j]);
        }

        if (t < 1) {
            float* asn = As[cur ^ 1]; float* wsn = Ws[cur ^ 1];
            asn[(ka+0)*132+lr]=a0.x; asn[(ka+1)*132+lr]=a0.y; asn[(ka+2)*132+lr]=a0.z; asn[(ka+3)*132+lr]=a0.w;
            asn[(ka+4)*132+lr]=a1.x; asn[(ka+5)*132+lr]=a1.y; asn[(ka+6)*132+lr]=a1.z; asn[(ka+7)*132+lr]=a1.w;
            wsn[(ka+0)*132+lr]=w0.x; wsn[(ka+1)*132+lr]=w0.y; wsn[(ka+2)*132+lr]=w0.z; wsn[(ka+3)*132+lr]=w0.w;
            wsn[(ka+4)*132+lr]=w1.x; wsn[(ka+5)*132+lr]=w1.y; wsn[(ka+6)*132+lr]=w1.z; wsn[(ka+7)*132+lr]=w1.w;
            __syncthreads();
        }
    }

    #pragma unroll
    for (int i = 0; i < 8; i++) {
        const int row = (ty << 3) + i;
        *(float4*)(outp + row * 1024 + n0 + (tx << 3)) =
            make_float4(acc[i][0], acc[i][1], acc[i][2], acc[i][3]);
        *(float4*)(outp + row * 1024 + n0 + (tx << 3) + 4) =
            make_float4(acc[i][4], acc[i][5], acc[i][6], acc[i][7]);
    }
}

// ---------------------------------------------------------------------------
// GEMM2 pass: one 64m x 64j pre-activation tile over full K=1024 (x | d_hv).
// Waits for the epilogue flag once, right before the h-half prefetch.
// ---------------------------------------------------------------------------
__device__ __forceinline__ void gemm2_pass(
    const float* __restrict__ x,
    const float* __restrict__ Wxp, const float* __restrict__ Whp,
    int j0, int m0, float* As, float* Ws, int tid, float acc[4][4])
{
    const int lm  = tid & 63;
    const int lk4 = (tid >> 6) << 2;
    const int tx  = tid & 15;
    const int ty  = tid >> 4;

    float4 av = *(const float4*)(x   + (m0 + lm) * 512 + lk4);
    float4 wv = *(const float4*)(Wxp + (j0 + lm) * 512 + lk4);

    for (int kt = 0; kt < 1024; kt += 16) {
        __syncthreads();
        As[(lk4+0)*68+lm]=av.x; As[(lk4+1)*68+lm]=av.y;
        As[(lk4+2)*68+lm]=av.z; As[(lk4+3)*68+lm]=av.w;
        Ws[(lk4+0)*68+lm]=wv.x; Ws[(lk4+1)*68+lm]=wv.y;
        Ws[(lk4+2)*68+lm]=wv.z; Ws[(lk4+3)*68+lm]=wv.w;
        __syncthreads();

        const int kn = kt + 16;
        if (kn == 512) wait_done(EPI_BLOCKS);   // d_hv must be ready
        if (kn < 1024) {
            if (kn < 512) {
                av = *(const float4*)(x   + (m0 + lm) * 512 + kn + lk4);
                wv = *(const float4*)(Wxp + (j0 + lm) * 512 + kn + lk4);
            } else {
                const int k2 = kn - 512;
                av = *(const float4*)(d_hv + (m0 + lm) * 512 + k2 + lk4);
                wv = *(const float4*)(Whp + (j0 + lm) * 512 + k2 + lk4);
            }
        }

        #pragma unroll
        for (int kk = 0; kk < 16; kk++) {
            const float4 a = *(const float4*)&As[kk*68 + (ty<<2)];
            const float4 w = *(const float4*)&Ws[kk*68 + (tx<<2)];
            acc[0][0]=fmaf(a.x,w.x,acc[0][0]); acc[0][1]=fmaf(a.x,w.y,acc[0][1]);
            acc[0][2]=fmaf(a.x,w.z,acc[0][2]); acc[0][3]=fmaf(a.x,w.w,acc[0][3]);
            acc[1][0]=fmaf(a.y,w.x,acc[1][0]); acc[1][1]=fmaf(a.y,w.y,acc[1][1]);
            acc[1][2]=fmaf(a.y,w.z,acc[1][2]); acc[1][3]=fmaf(a.y,w.w,acc[1][3]);
            acc[2][0]=fmaf(a.z,w.x,acc[2][0]); acc[2][1]=fmaf(a.z,w.y,acc[2][1]);
            acc[2][2]=fmaf(a.z,w.z,acc[2][2]); acc[2][3]=fmaf(a.z,w.w,acc[2][3]);
            acc[3][0]=fmaf(a.w,w.x,acc[3][0]); acc[3][1]=fmaf(a.w,w.y,acc[3][1]);
            acc[3][2]=fmaf(a.w,w.z,acc[3][2]); acc[3][3]=fmaf(a.w,w.w,acc[3][3]);
        }
    }
}

// ---------------------------------------------------------------------------
// Launch 2: FUSED kernel, <=64 regs (launch_bounds(256,4)), trace 4 CTAs/SM.
//   blocks [0,256)         : gate epilogue (partials -> gates/coeffs/outputs)
//   blocks [256,272)       : GEMM2 pass P -> tanh(p_pre) -> d_pfull + flag
//   blocks [272,288)       : GEMM2 pass O -> out (polls P flag, self-resets)
//   blocks [288,288+32768) : trace stream (loads FIRST, then flag, then FMA)
//   last block             : openings scalar
// ---------------------------------------------------------------------------
__global__ void __launch_bounds__(256, 4) k_fused(
    const float* __restrict__ x,  const float* __restrict__ h_last,
    const float* __restrict__ w_px, const float* __restrict__ w_ph,
    const float* __restrict__ w_ox, const float* __restrict__ w_oh,
    const float* __restrict__ b_g,  const float* __restrict__ b_r,
    const float* __restrict__ b_p,  const float* __restrict__ b_o,
    const float* __restrict__ e_b_g, const float* __restrict__ e_b_r,
    const float* __restrict__ egx, const float* __restrict__ egh,
    const float* __restrict__ erx, const float* __restrict__ erh,
    float* __restrict__ ogx, float* __restrict__ ogh,
    float* __restrict__ orx, float* __restrict__ orh,
    float* __restrict__ o_out, float* __restrict__ o_h,
    float* __restrict__ o_ebg, float* __restrict__ o_ebr,
    float* __restrict__ o_open)
{
    __shared__ float sA[16 * 68];
    __shared__ float sB[16 * 68];
    const int bx  = blockIdx.x;
    const int tid = threadIdx.x;

    if (bx >= TRACE_BASE && bx < TRACE_BASE + TRACE_BLOCKS) {
        // ---------------- trace stream: loads first, wait, FMA+store ----------
        const int idx = (bx - TRACE_BASE) * 256 + tid;
        const int i   = (idx & 127) << 2;
        const int bj  = idx >> 7;
        const int b   = bj >> 9;
        const int off = (bj << 9) + i;

        const float4 e0 = *(const float4*)(egx + off);
        const float4 e1 = *(const float4*)(egh + off);
        const float4 e2 = *(const float4*)(erx + off);
        const float4 e3 = *(const float4*)(erh + off);
        const float4 xv = *(const float4*)(x  + (b << 9) + i);
        const float4 hv = *(const float4*)(h_last + (b << 9) + i);

        wait_done(EPI_BLOCKS);           // coefficients ready (~4us after start)

        const float a  = d_av[bj];
        const float cg = d_cgv[bj];
        const float cr = d_crv[bj];

        float4 t;
        t.x = e0.x * a + cg * xv.x; t.y = e0.y * a + cg * xv.y;
        t.z = e0.z * a + cg * xv.z; t.w = e0.w * a + cg * xv.w;
        *(float4*)(ogx + off) = t;

        t.x = e1.x * a + cg * hv.x; t.y = e1.y * a + cg * hv.y;
        t.z = e1.z * a + cg * hv.z; t.w = e1.w * a + cg * hv.w;
        *(float4*)(ogh + off) = t;

        t.x = e2.x * a + cr * xv.x; t.y = e2.y * a + cr * xv.y;
        t.z = e2.z * a + cr * xv.z; t.w = e2.w * a + cr * xv.w;
        *(float4*)(orx + off) = t;

        t.x = e3.x * a + cr * hv.x; t.y = e3.y * a + cr * hv.y;
        t.z = e3.z * a + cr * hv.z; t.w = e3.w * a + cr * hv.w;
        *(float4*)(orh + off) = t;

    } else if (bx < EPI_BLOCKS) {
        // ---------------- gate epilogue (R12-proven math) ---------------------
        __shared__ int scnt[8];
        const int idx = bx * 256 + tid;      // b*512 + j
        const int b = idx >> 9;
        const int j = idx & 511;
        const int og  = b * 1024 + j;
        const int orr = og + 512;

        float gpre = b_g[j], rpre = b_r[j];
        #pragma unroll
        for (int p = 0; p < NSPLIT; p++) {
            gpre += d_part[p][og];
            rpre += d_part[p][orr];
        }

        float g = tanhf(gpre);
        g = fmaxf(g, 0.f);                   // relu(tanh)
        const float r  = tanhf(rpre);
        const float hl = h_last[idx];
        const float h  = g * r + (1.f - g) * hl;
        const float Hg = (g > 0.f) ? 1.f : 0.f;
        const float dg = (1.f - g * g) * Hg;
        const float dr = 1.f - r * r;
        const float a  = 1.f - g;
        const float cg = dg * (r - hl);
        const float cr = dr * g;

        d_av[idx]  = a;
        d_cgv[idx] = cg;
        d_crv[idx] = cr;
        d_hv[idx]  = h;

        o_h[idx]   = h;
        o_ebg[idx] = e_b_g[idx] * a + cg;
        o_ebr[idx] = e_b_r[idx] * a + cr;

        const int cnt = __popc(__ballot_sync(0xffffffffu, g > 0.f));
        if ((tid & 31) == 0) scnt[tid >> 5] = cnt;
        __syncthreads();
        if (tid == 0) {
            int t = 0;
            #pragma unroll
            for (int w = 0; w < 8; w++) t += scnt[w];
            d_cnt[bx] = t;
        }

        // release: coefficients visible, then count up
        __threadfence();
        __syncthreads();
        if (tid == 0) atomicAdd(&d_done, 1);

    } else if (bx < G2O_BASE) {
        // ---------------- GEMM2 pass P ----------------
        const int i2 = bx - G2P_BASE;
        const int j0 = (i2 & 7) * 64;
        const int m0 = (i2 >> 3) * 64;

        float acc[4][4];
        #pragma unroll
        for (int i = 0; i < 4; i++)
            #pragma unroll
            for (int j = 0; j < 4; j++) acc[i][j] = 0.f;

        gemm2_pass(x, w_px, w_ph, j0, m0, sA, sB, tid, acc);

        const int tx = tid & 15, ty = tid >> 4;
        #pragma unroll
        for (int i = 0; i < 4; i++)
            #pragma unroll
            for (int j = 0; j < 4; j++) {
                const int jj = j0 + (tx << 2) + j;
                d_pfull[(m0 + (ty << 2) + i) * 512 + jj] = tanhf(acc[i][j] + b_p[jj]);
            }
        __threadfence();
        __syncthreads();
        if (tid == 0) atomicExch(&d_pdone[i2], 1);

    } else if (bx < TRACE_BASE) {
        // ---------------- GEMM2 pass O ----------------
        const int i2 = bx - G2O_BASE;
        const int j0 = (i2 & 7) * 64;
        const int m0 = (i2 >> 3) * 64;

        float acc[4][4];
        #pragma unroll
        for (int i = 0; i < 4; i++)
            #pragma unroll
            for (int j = 0; j < 4; j++) acc[i][j] = 0.f;

        gemm2_pass(x, w_ox, w_oh, j0, m0, sA, sB, tid, acc);

        if (tid == 0) {
            while (atomicAdd(&d_pdone[i2], 0) == 0) __nanosleep(64);
            atomicExch(&d_pdone[i2], 0);     // self-reset for next replay
            __threadfence();
        }
        __syncthreads();

        const int tx = tid & 15, ty = tid >> 4;
        #pragma unroll
        for (int i = 0; i < 4; i++) {
            float4 v;
            #pragma unroll
            for (int j = 0; j < 4; j++) {
                const int jj = j0 + (tx << 2) + j;
                const int ro = (m0 + (ty << 2) + i) * 512 + jj;
                const float oval = 1.f / (1.f + expf(-(acc[i][j] + b_o[jj])));
                ((float*)&v)[j] = oval * d_pfull[ro];
            }
            *(float4*)(o_out + (m0 + (ty << 2) + i) * 512 + j0 + (tx << 2)) = v;
        }

    } else {
        // ---------------- openings ----------------
        wait_done(EPI_BLOCKS);
        __shared__ int scnt2[256];
        scnt2[tid] = d_cnt[tid];
        __syncthreads();
        for (int st = 128; st > 0; st >>= 1) {
            if (tid < st) scnt2[tid] += scnt2[tid + st];
            __syncthreads();
        }
        if (tid == 0)
            o_open[0] = (float)scnt2[0] * (1.f / (float)GATE_ELEMS);
    }
}

// ---------------------------------------------------------------------------
extern "C" void kernel_launch(void* const* d_in, const int* in_sizes, int n_in,
                              void* d_out, int out_size)
{
    const float* x      = (const float*)d_in[0];
    const float* h_last = (const float*)d_in[1];
    const float* w_gx   = (const float*)d_in[2];
    const float* w_gh   = (const float*)d_in[3];
    const float* b_g    = (const float*)d_in[4];
    const float* w_rx   = (const float*)d_in[5];
    const float* w_rh   = (const float*)d_in[6];
    const float* b_r    = (const float*)d_in[7];
    const float* w_px   = (const float*)d_in[8];
    const float* w_ph   = (const float*)d_in[9];
    const float* b_p    = (const float*)d_in[10];
    const float* w_ox   = (const float*)d_in[11];
    const float* w_oh   = (const float*)d_in[12];
    const float* b_o    = (const float*)d_in[13];
    const float* e_w_gx = (const float*)d_in[14];
    const float* e_w_gh = (const float*)d_in[15];
    const float* e_b_g  = (const float*)d_in[16];
    const float* e_w_rx = (const float*)d_in[17];
    const float* e_w_rh = (const float*)d_in[18];
    const float* e_b_r  = (const float*)d_in[19];

    float* out    = (float*)d_out;
    float* o_out  = out;                  // (128,512)
    float* o_h    = out + 65536;          // (128,512)
    float* o_egx  = out + 131072;         // (128,512,512)
    float* o_egh  = out + 33685504;       // (128,512,512)
    float* o_ebg  = out + 67239936;       // (128,512)
    float* o_erx  = out + 67305472;       // (128,512,512)
    float* o_erh  = out + 100859904;      // (128,512,512)
    float* o_ebr  = out + 134414336;      // (128,512)
    float* o_open = out + 134479872;      // scalar

    // Launch 1: g/r GEMM partials only (split-K=32, 256 CTAs, 2/SM)
    k_gemm1<<<dim3(8, NSPLIT), 256>>>(x, h_last, w_gx, w_gh, w_rx, w_rh);

    // Launch 2: gate epilogue + parallel P/O GEMM + trace streamer + openings
    k_fused<<<TRACE_BASE + TRACE_BLOCKS + 1, 256>>>(
        x, h_last, w_px, w_ph, w_ox, w_oh,
        b_g, b_r, b_p, b_o, e_b_g, e_b_r,
        e_w_gx, e_w_gh, e_w_rx, e_w_rh,
        o_egx, o_egh, o_erx, o_erh,
        o_out, o_h, o_ebg, o_ebr, o_open);
}

// round 16
// speedup vs baseline: 1.2194x; 1.2194x over previous
#include <cuda_runtime.h>
#include <math.h>

#define NB   128
#define NHID 512
#define GATE_ELEMS (NB * NHID)   // 65536
#define NSPLIT 32
#define GEMM1_BLOCKS (8 * NSPLIT)  // 256, all co-resident at 2 CTAs/SM
#define G2_BLOCKS 16               // per pass; P and O run as parallel blocks
#define TRACE_BLOCKS 32768
#define TRACE_BASE (2 * G2_BLOCKS) // 32

// ---------------- device scratch (no allocations allowed) ----------------
__device__ float d_part[NSPLIT][NB * 1024];  // split-K partials, 16 MB
__device__ float d_av  [GATE_ELEMS];         // 1 - g
__device__ float d_cgv [GATE_ELEMS];         // dg * delta_h
__device__ float d_crv [GATE_ELEMS];         // dr * g
__device__ float d_hv  [GATE_ELEMS];         // new h
__device__ float d_pfull[GATE_ELEMS];        // tanh(p_pre), written by P-blocks
__device__ int   d_cnt [GEMM1_BLOCKS];       // per-block open counts
__device__ int   d_done;                     // grid barrier ctr (reset by k_fused)
__device__ int   d_pdone[G2_BLOCKS];         // P-tile flags (self-reset by O-blocks)

// ---------------------------------------------------------------------------
// Launch 1: split-K dual GEMM for g/r pre-activations + in-kernel gate epilogue.
//   CTA tile 128m x 128n, BK=16, 8x8 register tile, double-buffered.
//   grid = (8 n-tiles, 32 splits) = 256 CTAs, 2 resident/SM (guaranteed).
//   Micro-opts vs R12: epilogue's partial-independent loads hoisted above the
//   grid barrier; nanosleep backoff in the barrier spin.
// ---------------------------------------------------------------------------
__global__ void __launch_bounds__(256, 2) k_gemm1(
    const float* __restrict__ x, const float* __restrict__ h_last,
    const float* __restrict__ w_gx, const float* __restrict__ w_gh,
    const float* __restrict__ w_rx, const float* __restrict__ w_rh,
    const float* __restrict__ b_g,  const float* __restrict__ b_r,
    const float* __restrict__ e_b_g, const float* __restrict__ e_b_r,
    float* __restrict__ out_h, float* __restrict__ out_ebg,
    float* __restrict__ out_ebr)
{
    __shared__ float As[2][16 * 132];   // [stage][k][m(128)+pad]
    __shared__ float Ws[2][16 * 132];   // [stage][k][n(128)+pad]

    const int tid  = threadIdx.x;
    const int n0   = blockIdx.x * 128;   // n in [0,1024)
    const int s    = blockIdx.y;         // split 0..31
    const int half = s >> 4;             // 0: x-part, 1: h-part
    const int kb   = (s & 15) * 32;      // offset within the 512-wide half

    const bool g2 = (n0 >= 512);
    const int  j0 = g2 ? (n0 - 512) : n0;
    const float* A = half ? h_last : x;
    const float* W = g2 ? (half ? w_rh : w_rx) : (half ? w_gh : w_gx);
    float* outp    = d_part[s];

    const int lr = tid & 127;            // row (m for A, n for W)
    const int ka = (tid >> 7) << 3;      // k offset: 0 or 8 (two float4 each)

    const int tx = tid & 15;             // n-dir (8 cols)
    const int ty = tid >> 4;             // m-dir (8 rows)

    const float* Aload = A + lr * 512 + kb + ka;
    const float* Wload = W + (j0 + lr) * 512 + kb + ka;

    float acc[8][8];
    #pragma unroll
    for (int i = 0; i < 8; i++)
        #pragma unroll
        for (int j = 0; j < 8; j++) acc[i][j] = 0.f;

    float4 a0 = *(const float4*)(Aload);
    float4 a1 = *(const float4*)(Aload + 4);
    float4 w0 = *(const float4*)(Wload);
    float4 w1 = *(const float4*)(Wload + 4);

    {
        float* as = As[0]; float* ws = Ws[0];
        as[(ka+0)*132+lr]=a0.x; as[(ka+1)*132+lr]=a0.y; as[(ka+2)*132+lr]=a0.z; as[(ka+3)*132+lr]=a0.w;
        as[(ka+4)*132+lr]=a1.x; as[(ka+5)*132+lr]=a1.y; as[(ka+6)*132+lr]=a1.z; as[(ka+7)*132+lr]=a1.w;
        ws[(ka+0)*132+lr]=w0.x; ws[(ka+1)*132+lr]=w0.y; ws[(ka+2)*132+lr]=w0.z; ws[(ka+3)*132+lr]=w0.w;
        ws[(ka+4)*132+lr]=w1.x; ws[(ka+5)*132+lr]=w1.y; ws[(ka+6)*132+lr]=w1.z; ws[(ka+7)*132+lr]=w1.w;
    }
    __syncthreads();

    #pragma unroll 1
    for (int t = 0; t < 2; t++) {        // 2 k-tiles of 16 (k-chunk = 32)
        const int cur = t & 1;
        const float* as = As[cur];
        const float* ws = Ws[cur];

        if (t < 1) {                      // prefetch next k-tile
            a0 = *(const float4*)(Aload + 16);
            a1 = *(const float4*)(Aload + 20);
            w0 = *(const float4*)(Wload + 16);
            w1 = *(const float4*)(Wload + 20);
        }

        #pragma unroll
        for (int kk = 0; kk < 16; kk++) {
            float a[8], w[8];
            *(float4*)&a[0] = *(const float4*)(as + kk * 132 + (ty << 3));
            *(float4*)&a[4] = *(const float4*)(as + kk * 132 + (ty << 3) + 4);
            *(float4*)&w[0] = *(const float4*)(ws + kk * 132 + (tx << 3));
            *(float4*)&w[4] = *(const float4*)(ws + kk * 132 + (tx << 3) + 4);
            #pragma unroll
            for (int i = 0; i < 8; i++)
                #pragma unroll
                for (int j = 0; j < 8; j++)
                    acc[i][j] = fmaf(a[i], w[j], acc[i][j]);
        }

        if (t < 1) {
            float* asn = As[cur ^ 1]; float* wsn = Ws[cur ^ 1];
            asn[(ka+0)*132+lr]=a0.x; asn[(ka+1)*132+lr]=a0.y; asn[(ka+2)*132+lr]=a0.z; asn[(ka+3)*132+lr]=a0.w;
            asn[(ka+4)*132+lr]=a1.x; asn[(ka+5)*132+lr]=a1.y; asn[(ka+6)*132+lr]=a1.z; asn[(ka+7)*132+lr]=a1.w;
            wsn[(ka+0)*132+lr]=w0.x; wsn[(ka+1)*132+lr]=w0.y; wsn[(ka+2)*132+lr]=w0.z; wsn[(ka+3)*132+lr]=w0.w;
            wsn[(ka+4)*132+lr]=w1.x; wsn[(ka+5)*132+lr]=w1.y; wsn[(ka+6)*132+lr]=w1.z; wsn[(ka+7)*132+lr]=w1.w;
            __syncthreads();
        }
    }

    #pragma unroll
    for (int i = 0; i < 8; i++) {
        const int row = (ty << 3) + i;
        *(float4*)(outp + row * 1024 + n0 + (tx << 3)) =
            make_float4(acc[i][0], acc[i][1], acc[i][2], acc[i][3]);
        *(float4*)(outp + row * 1024 + n0 + (tx << 3) + 4) =
            make_float4(acc[i][4], acc[i][5], acc[i][6], acc[i][7]);
    }

    // ---- hoist epilogue loads that don't depend on the partials ----
    const int blk = blockIdx.y * 8 + blockIdx.x;   // 0..255
    const int idx = blk * 256 + tid;               // b*512 + j
    const float hl     = h_last[idx];
    const float ebg_in = e_b_g[idx];
    const float ebr_in = e_b_r[idx];

    // ---- device-wide barrier: all 256 CTAs are co-resident (2/SM) ----
    __threadfence();
    __syncthreads();
    if (tid == 0) {
        atomicAdd(&d_done, 1);
        while (atomicAdd(&d_done, 0) < GEMM1_BLOCKS) __nanosleep(32);
        __threadfence();
    }
    __syncthreads();

    // ---- gate epilogue: this block's 256 elements ----
    __shared__ int scnt[8];
    const int b = idx >> 9;
    const int j = idx & 511;
    const int og  = b * 1024 + j;
    const int orr = og + 512;

    float gpre = b_g[j], rpre = b_r[j];
    #pragma unroll
    for (int p = 0; p < NSPLIT; p++) {
        gpre += d_part[p][og];
        rpre += d_part[p][orr];
    }

    float g = tanhf(gpre);
    g = fmaxf(g, 0.f);                      // relu(tanh)
    const float r  = tanhf(rpre);
    const float h  = g * r + (1.f - g) * hl;
    const float Hg = (g > 0.f) ? 1.f : 0.f; // clip(ceil(g),0,1), g in [0,1]
    const float dg = (1.f - g * g) * Hg;
    const float dr = 1.f - r * r;
    const float a  = 1.f - g;
    const float cg = dg * (r - hl);
    const float cr = dr * g;

    d_av[idx]  = a;
    d_cgv[idx] = cg;
    d_crv[idx] = cr;
    d_hv[idx]  = h;

    out_h[idx]   = h;
    out_ebg[idx] = ebg_in * a + cg;
    out_ebr[idx] = ebr_in * a + cr;

    const int cnt = __popc(__ballot_sync(0xffffffffu, g > 0.f));
    if ((tid & 31) == 0) scnt[tid >> 5] = cnt;
    __syncthreads();
    if (tid == 0) {
        int t = 0;
        #pragma unroll
        for (int w = 0; w < 8; w++) t += scnt[w];
        d_cnt[blk] = t;
    }
}

// ---------------------------------------------------------------------------
// GEMM2 pass: one 64m x 64j pre-activation tile over full K=1024 (x | d_hv).
// d_hv is complete (written in launch 1), so no flags inside the loop.
// 16 accumulators -> fits the 64-reg budget of k_fused.
// ---------------------------------------------------------------------------
__device__ __forceinline__ void gemm2_pass(
    const float* __restrict__ x,
    const float* __restrict__ Wxp, const float* __restrict__ Whp,
    int j0, int m0, float* As, float* Ws, int tid, float acc[4][4])
{
    const int lm  = tid & 63;
    const int lk4 = (tid >> 6) << 2;
    const int tx  = tid & 15;
    const int ty  = tid >> 4;

    float4 av = *(const float4*)(x   + (m0 + lm) * 512 + lk4);
    float4 wv = *(const float4*)(Wxp + (j0 + lm) * 512 + lk4);

    for (int kt = 0; kt < 1024; kt += 16) {
        __syncthreads();
        As[(lk4+0)*68+lm]=av.x; As[(lk4+1)*68+lm]=av.y;
        As[(lk4+2)*68+lm]=av.z; As[(lk4+3)*68+lm]=av.w;
        Ws[(lk4+0)*68+lm]=wv.x; Ws[(lk4+1)*68+lm]=wv.y;
        Ws[(lk4+2)*68+lm]=wv.z; Ws[(lk4+3)*68+lm]=wv.w;
        __syncthreads();

        const int kn = kt + 16;
        if (kn < 1024) {
            if (kn < 512) {
                av = *(const float4*)(x   + (m0 + lm) * 512 + kn + lk4);
                wv = *(const float4*)(Wxp + (j0 + lm) * 512 + kn + lk4);
            } else {
                const int k2 = kn - 512;
                av = *(const float4*)(d_hv + (m0 + lm) * 512 + k2 + lk4);
                wv = *(const float4*)(Whp + (j0 + lm) * 512 + k2 + lk4);
            }
        }

        #pragma unroll
        for (int kk = 0; kk < 16; kk++) {
            const float4 a = *(const float4*)&As[kk*68 + (ty<<2)];
            const float4 w = *(const float4*)&Ws[kk*68 + (tx<<2)];
            acc[0][0]=fmaf(a.x,w.x,acc[0][0]); acc[0][1]=fmaf(a.x,w.y,acc[0][1]);
            acc[0][2]=fmaf(a.x,w.z,acc[0][2]); acc[0][3]=fmaf(a.x,w.w,acc[0][3]);
            acc[1][0]=fmaf(a.y,w.x,acc[1][0]); acc[1][1]=fmaf(a.y,w.y,acc[1][1]);
            acc[1][2]=fmaf(a.y,w.z,acc[1][2]); acc[1][3]=fmaf(a.y,w.w,acc[1][3]);
            acc[2][0]=fmaf(a.z,w.x,acc[2][0]); acc[2][1]=fmaf(a.z,w.y,acc[2][1]);
            acc[2][2]=fmaf(a.z,w.z,acc[2][2]); acc[2][3]=fmaf(a.z,w.w,acc[2][3]);
            acc[3][0]=fmaf(a.w,w.x,acc[3][0]); acc[3][1]=fmaf(a.w,w.y,acc[3][1]);
            acc[3][2]=fmaf(a.w,w.z,acc[3][2]); acc[3][3]=fmaf(a.w,w.w,acc[3][3]);
        }
    }
}

// ---------------------------------------------------------------------------
// Launch 2: FUSED kernel, <=64 regs (launch_bounds(256,4)) so trace blocks
// run 4 CTAs/SM. (R12-validated, unchanged.)
//   blocks [0,16)          : GEMM2 pass P -> tanh(p_pre) -> d_pfull + flag
//   blocks [16,32)         : GEMM2 pass O -> poll flag -> out (self-reset flag)
//   blocks [32, 32+32768)  : HBM-bound trace update (batched loads)
//   last block             : openings scalar + reset d_done
// ---------------------------------------------------------------------------
__global__ void __launch_bounds__(256, 4) k_fused(
    const float* __restrict__ x,  const float* __restrict__ h_last,
    const float* __restrict__ w_px, const float* __restrict__ w_ph,
    const float* __restrict__ w_ox, const float* __restrict__ w_oh,
    const float* __restrict__ b_p,  const float* __restrict__ b_o,
    const float* __restrict__ egx, const float* __restrict__ egh,
    const float* __restrict__ erx, const float* __restrict__ erh,
    float* __restrict__ ogx, float* __restrict__ ogh,
    float* __restrict__ orx, float* __restrict__ orh,
    float* __restrict__ o_out, float* __restrict__ o_open)
{
    __shared__ float sA[16 * 68];
    __shared__ float sB[16 * 68];
    const int bx  = blockIdx.x;
    const int tid = threadIdx.x;

    if (bx < G2_BLOCKS) {
        // ---------------- GEMM2 pass P ----------------
        const int i2 = bx;
        const int j0 = (i2 & 7) * 64;
        const int m0 = (i2 >> 3) * 64;

        float acc[4][4];
        #pragma unroll
        for (int i = 0; i < 4; i++)
            #pragma unroll
            for (int j = 0; j < 4; j++) acc[i][j] = 0.f;

        gemm2_pass(x, w_px, w_ph, j0, m0, sA, sB, tid, acc);

        const int tx = tid & 15, ty = tid >> 4;
        #pragma unroll
        for (int i = 0; i < 4; i++)
            #pragma unroll
            for (int j = 0; j < 4; j++) {
                const int jj = j0 + (tx << 2) + j;
                d_pfull[(m0 + (ty << 2) + i) * 512 + jj] = tanhf(acc[i][j] + b_p[jj]);
            }
        __threadfence();
        __syncthreads();
        if (tid == 0) atomicExch(&d_pdone[i2], 1);

    } else if (bx < TRACE_BASE) {
        // ---------------- GEMM2 pass O ----------------
        const int i2 = bx - G2_BLOCKS;
        const int j0 = (i2 & 7) * 64;
        const int m0 = (i2 >> 3) * 64;

        float acc[4][4];
        #pragma unroll
        for (int i = 0; i < 4; i++)
            #pragma unroll
            for (int j = 0; j < 4; j++) acc[i][j] = 0.f;

        gemm2_pass(x, w_ox, w_oh, j0, m0, sA, sB, tid, acc);

        if (tid == 0) {
            while (atomicAdd(&d_pdone[i2], 0) == 0) __nanosleep(64);
            atomicExch(&d_pdone[i2], 0);     // self-reset for next replay
            __threadfence();
        }
        __syncthreads();

        const int tx = tid & 15, ty = tid >> 4;
        #pragma unroll
        for (int i = 0; i < 4; i++) {
            float4 v;
            #pragma unroll
            for (int j = 0; j < 4; j++) {
                const int jj = j0 + (tx << 2) + j;
                const int ro = (m0 + (ty << 2) + i) * 512 + jj;
                const float oval = 1.f / (1.f + expf(-(acc[i][j] + b_o[jj])));
                ((float*)&v)[j] = oval * d_pfull[ro];
            }
            *(float4*)(o_out + (m0 + (ty << 2) + i) * 512 + j0 + (tx << 2)) = v;
        }

    } else if (bx < TRACE_BASE + TRACE_BLOCKS) {
        // ---------------- trace stream (batched loads, no dependencies) -------
        const int idx = (bx - TRACE_BASE) * 256 + tid;
        const int i   = (idx & 127) << 2;
        const int bj  = idx >> 7;
        const int b   = bj >> 9;
        const int off = (bj << 9) + i;

        const float4 e0 = *(const float4*)(egx + off);
        const float4 e1 = *(const float4*)(egh + off);
        const float4 e2 = *(const float4*)(erx + off);
        const float4 e3 = *(const float4*)(erh + off);
        const float4 xv = *(const float4*)(x  + (b << 9) + i);
        const float4 hv = *(const float4*)(h_last + (b << 9) + i);
        const float a  = __ldg(&d_av[bj]);
        const float cg = __ldg(&d_cgv[bj]);
        const float cr = __ldg(&d_crv[bj]);

        float4 t;
        t.x = e0.x * a + cg * xv.x; t.y = e0.y * a + cg * xv.y;
        t.z = e0.z * a + cg * xv.z; t.w = e0.w * a + cg * xv.w;
        *(float4*)(ogx + off) = t;

        t.x = e1.x * a + cg * hv.x; t.y = e1.y * a + cg * hv.y;
        t.z = e1.z * a + cg * hv.z; t.w = e1.w * a + cg * hv.w;
        *(float4*)(ogh + off) = t;

        t.x = e2.x * a + cr * xv.x; t.y = e2.y * a + cr * xv.y;
        t.z = e2.z * a + cr * xv.z; t.w = e2.w * a + cr * xv.w;
        *(float4*)(orx + off) = t;

        t.x = e3.x * a + cr * hv.x; t.y = e3.y * a + cr * hv.y;
        t.z = e3.z * a + cr * hv.z; t.w = e3.w * a + cr * hv.w;
        *(float4*)(orh + off) = t;

    } else {
        // ---------------- openings + barrier reset ----------------
        __shared__ int scnt[256];
        scnt[tid] = d_cnt[tid];
        __syncthreads();
        for (int st = 128; st > 0; st >>= 1) {
            if (tid < st) scnt[tid] += scnt[tid + st];
            __syncthreads();
        }
        if (tid == 0) {
            o_open[0] = (float)scnt[0] * (1.f / (float)GATE_ELEMS);
            d_done = 0;                  // reset grid barrier for next replay
        }
    }
}

// ---------------------------------------------------------------------------
extern "C" void kernel_launch(void* const* d_in, const int* in_sizes, int n_in,
                              void* d_out, int out_size)
{
    const float* x      = (const float*)d_in[0];
    const float* h_last = (const float*)d_in[1];
    const float* w_gx   = (const float*)d_in[2];
    const float* w_gh   = (const float*)d_in[3];
    const float* b_g    = (const float*)d_in[4];
    const float* w_rx   = (const float*)d_in[5];
    const float* w_rh   = (const float*)d_in[6];
    const float* b_r    = (const float*)d_in[7];
    const float* w_px   = (const float*)d_in[8];
    const float* w_ph   = (const float*)d_in[9];
    const float* b_p    = (const float*)d_in[10];
    const float* w_ox   = (const float*)d_in[11];
    const float* w_oh   = (const float*)d_in[12];
    const float* b_o    = (const float*)d_in[13];
    const float* e_w_gx = (const float*)d_in[14];
    const float* e_w_gh = (const float*)d_in[15];
    const float* e_b_g  = (const float*)d_in[16];
    const float* e_w_rx = (const float*)d_in[17];
    const float* e_w_rh = (const float*)d_in[18];
    const float* e_b_r  = (const float*)d_in[19];

    float* out    = (float*)d_out;
    float* o_out  = out;                  // (128,512)
    float* o_h    = out + 65536;          // (128,512)
    float* o_egx  = out + 131072;         // (128,512,512)
    float* o_egh  = out + 33685504;       // (128,512,512)
    float* o_ebg  = out + 67239936;       // (128,512)
    float* o_erx  = out + 67305472;       // (128,512,512)
    float* o_erh  = out + 100859904;      // (128,512,512)
    float* o_ebr  = out + 134414336;      // (128,512)
    float* o_open = out + 134479872;      // scalar

    // Launch 1: g/r GEMM (split-K=32, 256 CTAs, 2/SM) + in-kernel gate epilogue
    k_gemm1<<<dim3(8, NSPLIT), 256>>>(x, h_last, w_gx, w_gh, w_rx, w_rh,
                                      b_g, b_r, e_b_g, e_b_r,
                                      o_h, o_ebg, o_ebr);

    // Launch 2: parallel P/O GEMM blocks + trace streamer + openings
    k_fused<<<TRACE_BASE + TRACE_BLOCKS + 1, 256>>>(
        x, h_last, w_px, w_ph, w_ox, w_oh, b_p, b_o,
        e_w_gx, e_w_gh, e_w_rx, e_w_rh,
        o_egx, o_egh, o_erx, o_erh,
        o_out, o_open);
}

// round 17
// speedup vs baseline: 1.2487x; 1.0240x over previous
#include <cuda_runtime.h>
#include <math.h>

#define NB   128
#define NHID 512
#define GATE_ELEMS (NB * NHID)   // 65536
#define NSPLIT 16
#define GEMM1_BLOCKS (16 * NSPLIT) // 256, all co-resident at 2 CTAs/SM
#define G2_BLOCKS 16               // per pass; P and O run as parallel blocks
#define TRACE_BLOCKS 32768
#define TRACE_BASE (2 * G2_BLOCKS) // 32

// ---------------- device scratch (no allocations allowed) ----------------
__device__ float d_part[NSPLIT][NB * 1024];  // split-K partials, 8 MB
__device__ float d_av  [GATE_ELEMS];         // 1 - g
__device__ float d_cgv [GATE_ELEMS];         // dg * delta_h
__device__ float d_crv [GATE_ELEMS];         // dr * g
__device__ float d_hv  [GATE_ELEMS];         // new h
__device__ float d_pfull[GATE_ELEMS];        // tanh(p_pre), written by P-blocks
__device__ int   d_cnt [GEMM1_BLOCKS];       // per-block open counts
__device__ int   d_done;                     // grid barrier ctr (reset by k_fused)
__device__ int   d_pdone[G2_BLOCKS];         // P-tile flags (self-reset by O-blocks)

// ---------------------------------------------------------------------------
// Launch 1: split-K dual GEMM for g/r pre-activations + in-kernel gate epilogue.
//   CTA tile 128m x 64n, BK=16, k-chunk 64 (4 k-tiles), 8x4 register tile,
//   double-buffered. grid = (16 n-tiles, 16 splits) = 256 CTAs, 2/SM.
//   split s: half = s>>3 (x | h_last), kb = (s&7)*64.
// ---------------------------------------------------------------------------
__global__ void __launch_bounds__(256, 2) k_gemm1(
    const float* __restrict__ x, const float* __restrict__ h_last,
    const float* __restrict__ w_gx, const float* __restrict__ w_gh,
    const float* __restrict__ w_rx, const float* __restrict__ w_rh,
    const float* __restrict__ b_g,  const float* __restrict__ b_r,
    const float* __restrict__ e_b_g, const float* __restrict__ e_b_r,
    float* __restrict__ out_h, float* __restrict__ out_ebg,
    float* __restrict__ out_ebr)
{
    __shared__ float As[2][16 * 132];   // [stage][k][m(128)+pad]
    __shared__ float Ws[2][16 * 68];    // [stage][k][n(64)+pad]

    const int tid  = threadIdx.x;
    const int n0   = blockIdx.x * 64;    // n in [0,1024)
    const int s    = blockIdx.y;         // split 0..15
    const int half = s >> 3;             // 0: x-part, 1: h-part
    const int kb   = (s & 7) * 64;       // offset within the 512-wide half

    const bool g2 = (n0 >= 512);
    const int  j0 = g2 ? (n0 - 512) : n0;
    const float* A = half ? h_last : x;
    const float* W = g2 ? (half ? w_rh : w_rx) : (half ? w_gh : w_gx);
    float* outp    = d_part[s];

    // A loader: 128 rows x 16 k = 512 float4; 2 per thread (k offsets ka, ka+4)
    const int lr = tid & 127;
    const int ka = (tid >> 7) << 3;      // 0 or 8
    // W loader: 64 rows x 16 k = 256 float4; 1 per thread
    const int ln = tid & 63;
    const int kw = ((tid >> 6) & 3) << 2; // 0,4,8,12

    const int tx = tid & 15;             // n-dir (4 cols)
    const int ty = tid >> 4;             // m-dir (8 rows)

    const float* Aload = A + lr * 512 + kb + ka;
    const float* Wload = W + (j0 + ln) * 512 + kb + kw;

    float acc[8][4];
    #pragma unroll
    for (int i = 0; i < 8; i++)
        #pragma unroll
        for (int j = 0; j < 4; j++) acc[i][j] = 0.f;

    float4 a0 = *(const float4*)(Aload);
    float4 a1 = *(const float4*)(Aload + 4);
    float4 w0 = *(const float4*)(Wload);

    {
        float* as = As[0]; float* ws = Ws[0];
        as[(ka+0)*132+lr]=a0.x; as[(ka+1)*132+lr]=a0.y; as[(ka+2)*132+lr]=a0.z; as[(ka+3)*132+lr]=a0.w;
        as[(ka+4)*132+lr]=a1.x; as[(ka+5)*132+lr]=a1.y; as[(ka+6)*132+lr]=a1.z; as[(ka+7)*132+lr]=a1.w;
        ws[(kw+0)*68+ln]=w0.x; ws[(kw+1)*68+ln]=w0.y;
        ws[(kw+2)*68+ln]=w0.z; ws[(kw+3)*68+ln]=w0.w;
    }
    __syncthreads();

    #pragma unroll 1
    for (int t = 0; t < 4; t++) {        // 4 k-tiles of 16 (k-chunk = 64)
        const int cur = t & 1;
        const float* as = As[cur];
        const float* ws = Ws[cur];

        if (t < 3) {                      // prefetch next k-tile
            const int ko = (t + 1) * 16;
            a0 = *(const float4*)(Aload + ko);
            a1 = *(const float4*)(Aload + ko + 4);
            w0 = *(const float4*)(Wload + ko);
        }

        #pragma unroll
        for (int kk = 0; kk < 16; kk++) {
            float a[8], w[4];
            *(float4*)&a[0] = *(const float4*)(as + kk * 132 + (ty << 3));
            *(float4*)&a[4] = *(const float4*)(as + kk * 132 + (ty << 3) + 4);
            *(float4*)&w[0] = *(const float4*)(ws + kk * 68 + (tx << 2));
            #pragma unroll
            for (int i = 0; i < 8; i++)
                #pragma unroll
                for (int j = 0; j < 4; j++)
                    acc[i][j] = fmaf(a[i], w[j], acc[i][j]);
        }

        if (t < 3) {
            float* asn = As[cur ^ 1]; float* wsn = Ws[cur ^ 1];
            asn[(ka+0)*132+lr]=a0.x; asn[(ka+1)*132+lr]=a0.y; asn[(ka+2)*132+lr]=a0.z; asn[(ka+3)*132+lr]=a0.w;
            asn[(ka+4)*132+lr]=a1.x; asn[(ka+5)*132+lr]=a1.y; asn[(ka+6)*132+lr]=a1.z; asn[(ka+7)*132+lr]=a1.w;
            wsn[(kw+0)*68+ln]=w0.x; wsn[(kw+1)*68+ln]=w0.y;
            wsn[(kw+2)*68+ln]=w0.z; wsn[(kw+3)*68+ln]=w0.w;
            __syncthreads();
        }
    }

    #pragma unroll
    for (int i = 0; i < 8; i++) {
        const int row = (ty << 3) + i;
        *(float4*)(outp + row * 1024 + n0 + (tx << 2)) =
            make_float4(acc[i][0], acc[i][1], acc[i][2], acc[i][3]);
    }

    // ---- hoist epilogue loads that don't depend on the partials ----
    const int blk = blockIdx.y * 16 + blockIdx.x;  // 0..255
    const int idx = blk * 256 + tid;               // b*512 + j
    const float hl     = h_last[idx];
    const float ebg_in = e_b_g[idx];
    const float ebr_in = e_b_r[idx];

    // ---- device-wide barrier: all 256 CTAs are co-resident (2/SM) ----
    __threadfence();
    __syncthreads();
    if (tid == 0) {
        atomicAdd(&d_done, 1);
        while (atomicAdd(&d_done, 0) < GEMM1_BLOCKS) __nanosleep(32);
        __threadfence();
    }
    __syncthreads();

    // ---- gate epilogue: this block's 256 elements ----
    __shared__ int scnt[8];
    const int b = idx >> 9;
    const int j = idx & 511;
    const int og  = b * 1024 + j;
    const int orr = og + 512;

    float gpre = b_g[j], rpre = b_r[j];
    #pragma unroll
    for (int p = 0; p < NSPLIT; p++) {
        gpre += d_part[p][og];
        rpre += d_part[p][orr];
    }

    float g = tanhf(gpre);
    g = fmaxf(g, 0.f);                      // relu(tanh)
    const float r  = tanhf(rpre);
    const float h  = g * r + (1.f - g) * hl;
    const float Hg = (g > 0.f) ? 1.f : 0.f; // clip(ceil(g),0,1), g in [0,1]
    const float dg = (1.f - g * g) * Hg;
    const float dr = 1.f - r * r;
    const float a  = 1.f - g;
    const float cg = dg * (r - hl);
    const float cr = dr * g;

    d_av[idx]  = a;
    d_cgv[idx] = cg;
    d_crv[idx] = cr;
    d_hv[idx]  = h;

    out_h[idx]   = h;
    out_ebg[idx] = ebg_in * a + cg;
    out_ebr[idx] = ebr_in * a + cr;

    const int cnt = __popc(__ballot_sync(0xffffffffu, g > 0.f));
    if ((tid & 31) == 0) scnt[tid >> 5] = cnt;
    __syncthreads();
    if (tid == 0) {
        int t = 0;
        #pragma unroll
        for (int w = 0; w < 8; w++) t += scnt[w];
        d_cnt[blk] = t;
    }
}

// ---------------------------------------------------------------------------
// GEMM2 pass: one 64m x 64j pre-activation tile over full K=1024 (x | d_hv).
// d_hv complete (launch 1). 16 accumulators, fits 64-reg budget of k_fused.
// ---------------------------------------------------------------------------
__device__ __forceinline__ void gemm2_pass(
    const float* __restrict__ x,
    const float* __restrict__ Wxp, const float* __restrict__ Whp,
    int j0, int m0, float* As, float* Ws, int tid, float acc[4][4])
{
    const int lm  = tid & 63;
    const int lk4 = (tid >> 6) << 2;
    const int tx  = tid & 15;
    const int ty  = tid >> 4;

    float4 av = *(const float4*)(x   + (m0 + lm) * 512 + lk4);
    float4 wv = *(const float4*)(Wxp + (j0 + lm) * 512 + lk4);

    for (int kt = 0; kt < 1024; kt += 16) {
        __syncthreads();
        As[(lk4+0)*68+lm]=av.x; As[(lk4+1)*68+lm]=av.y;
        As[(lk4+2)*68+lm]=av.z; As[(lk4+3)*68+lm]=av.w;
        Ws[(lk4+0)*68+lm]=wv.x; Ws[(lk4+1)*68+lm]=wv.y;
        Ws[(lk4+2)*68+lm]=wv.z; Ws[(lk4+3)*68+lm]=wv.w;
        __syncthreads();

        const int kn = kt + 16;
        if (kn < 1024) {
            if (kn < 512) {
                av = *(const float4*)(x   + (m0 + lm) * 512 + kn + lk4);
                wv = *(const float4*)(Wxp + (j0 + lm) * 512 + kn + lk4);
            } else {
                const int k2 = kn - 512;
                av = *(const float4*)(d_hv + (m0 + lm) * 512 + k2 + lk4);
                wv = *(const float4*)(Whp + (j0 + lm) * 512 + k2 + lk4);
            }
        }

        #pragma unroll
        for (int kk = 0; kk < 16; kk++) {
            const float4 a = *(const float4*)&As[kk*68 + (ty<<2)];
            const float4 w = *(const float4*)&Ws[kk*68 + (tx<<2)];
            acc[0][0]=fmaf(a.x,w.x,acc[0][0]); acc[0][1]=fmaf(a.x,w.y,acc[0][1]);
            acc[0][2]=fmaf(a.x,w.z,acc[0][2]); acc[0][3]=fmaf(a.x,w.w,acc[0][3]);
            acc[1][0]=fmaf(a.y,w.x,acc[1][0]); acc[1][1]=fmaf(a.y,w.y,acc[1][1]);
            acc[1][2]=fmaf(a.y,w.z,acc[1][2]); acc[1][3]=fmaf(a.y,w.w,acc[1][3]);
            acc[2][0]=fmaf(a.z,w.x,acc[2][0]); acc[2][1]=fmaf(a.z,w.y,acc[2][1]);
            acc[2][2]=fmaf(a.z,w.z,acc[2][2]); acc[2][3]=fmaf(a.z,w.w,acc[2][3]);
            acc[3][0]=fmaf(a.w,w.x,acc[3][0]); acc[3][1]=fmaf(a.w,w.y,acc[3][1]);
            acc[3][2]=fmaf(a.w,w.z,acc[3][2]); acc[3][3]=fmaf(a.w,w.w,acc[3][3]);
        }
    }
}

// ---------------------------------------------------------------------------
// Launch 2: FUSED kernel, <=64 regs (launch_bounds(256,4)), trace 4 CTAs/SM.
// (R12-validated, unchanged.)
//   blocks [0,16)          : GEMM2 pass P -> tanh(p_pre) -> d_pfull + flag
//   blocks [16,32)         : GEMM2 pass O -> poll flag -> out (self-reset flag)
//   blocks [32, 32+32768)  : HBM-bound trace update (batched loads)
//   last block             : openings scalar + reset d_done
// ---------------------------------------------------------------------------
__global__ void __launch_bounds__(256, 4) k_fused(
    const float* __restrict__ x,  const float* __restrict__ h_last,
    const float* __restrict__ w_px, const float* __restrict__ w_ph,
    const float* __restrict__ w_ox, const float* __restrict__ w_oh,
    const float* __restrict__ b_p,  const float* __restrict__ b_o,
    const float* __restrict__ egx, const float* __restrict__ egh,
    const float* __restrict__ erx, const float* __restrict__ erh,
    float* __restrict__ ogx, float* __restrict__ ogh,
    float* __restrict__ orx, float* __restrict__ orh,
    float* __restrict__ o_out, float* __restrict__ o_open)
{
    __shared__ float sA[16 * 68];
    __shared__ float sB[16 * 68];
    const int bx  = blockIdx.x;
    const int tid = threadIdx.x;

    if (bx < G2_BLOCKS) {
        // ---------------- GEMM2 pass P ----------------
        const int i2 = bx;
        const int j0 = (i2 & 7) * 64;
        const int m0 = (i2 >> 3) * 64;

        float acc[4][4];
        #pragma unroll
        for (int i = 0; i < 4; i++)
            #pragma unroll
            for (int j = 0; j < 4; j++) acc[i][j] = 0.f;

        gemm2_pass(x, w_px, w_ph, j0, m0, sA, sB, tid, acc);

        const int tx = tid & 15, ty = tid >> 4;
        #pragma unroll
        for (int i = 0; i < 4; i++)
            #pragma unroll
            for (int j = 0; j < 4; j++) {
                const int jj = j0 + (tx << 2) + j;
                d_pfull[(m0 + (ty << 2) + i) * 512 + jj] = tanhf(acc[i][j] + b_p[jj]);
            }
        __threadfence();
        __syncthreads();
        if (tid == 0) atomicExch(&d_pdone[i2], 1);

    } else if (bx < TRACE_BASE) {
        // ---------------- GEMM2 pass O ----------------
        const int i2 = bx - G2_BLOCKS;
        const int j0 = (i2 & 7) * 64;
        const int m0 = (i2 >> 3) * 64;

        float acc[4][4];
        #pragma unroll
        for (int i = 0; i < 4; i++)
            #pragma unroll
            for (int j = 0; j < 4; j++) acc[i][j] = 0.f;

        gemm2_pass(x, w_ox, w_oh, j0, m0, sA, sB, tid, acc);

        if (tid == 0) {
            while (atomicAdd(&d_pdone[i2], 0) == 0) __nanosleep(64);
            atomicExch(&d_pdone[i2], 0);     // self-reset for next replay
            __threadfence();
        }
        __syncthreads();

        const int tx = tid & 15, ty = tid >> 4;
        #pragma unroll
        for (int i = 0; i < 4; i++) {
            float4 v;
            #pragma unroll
            for (int j = 0; j < 4; j++) {
                const int jj = j0 + (tx << 2) + j;
                const int ro = (m0 + (ty << 2) + i) * 512 + jj;
                const float oval = 1.f / (1.f + expf(-(acc[i][j] + b_o[jj])));
                ((float*)&v)[j] = oval * d_pfull[ro];
            }
            *(float4*)(o_out + (m0 + (ty << 2) + i) * 512 + j0 + (tx << 2)) = v;
        }

    } else if (bx < TRACE_BASE + TRACE_BLOCKS) {
        // ---------------- trace stream (batched loads, no dependencies) -------
        const int idx = (bx - TRACE_BASE) * 256 + tid;
        const int i   = (idx & 127) << 2;
        const int bj  = idx >> 7;
        const int b   = bj >> 9;
        const int off = (bj << 9) + i;

        const float4 e0 = *(const float4*)(egx + off);
        const float4 e1 = *(const float4*)(egh + off);
        const float4 e2 = *(const float4*)(erx + off);
        const float4 e3 = *(const float4*)(erh + off);
        const float4 xv = *(const float4*)(x  + (b << 9) + i);
        const float4 hv = *(const float4*)(h_last + (b << 9) + i);
        const float a  = __ldg(&d_av[bj]);
        const float cg = __ldg(&d_cgv[bj]);
        const float cr = __ldg(&d_crv[bj]);

        float4 t;
        t.x = e0.x * a + cg * xv.x; t.y = e0.y * a + cg * xv.y;
        t.z = e0.z * a + cg * xv.z; t.w = e0.w * a + cg * xv.w;
        *(float4*)(ogx + off) = t;

        t.x = e1.x * a + cg * hv.x; t.y = e1.y * a + cg * hv.y;
        t.z = e1.z * a + cg * hv.z; t.w = e1.w * a + cg * hv.w;
        *(float4*)(ogh + off) = t;

        t.x = e2.x * a + cr * xv.x; t.y = e2.y * a + cr * xv.y;
        t.z = e2.z * a + cr * xv.z; t.w = e2.w * a + cr * xv.w;
        *(float4*)(orx + off) = t;

        t.x = e3.x * a + cr * hv.x; t.y = e3.y * a + cr * hv.y;
        t.z = e3.z * a + cr * hv.z; t.w = e3.w * a + cr * hv.w;
        *(float4*)(orh + off) = t;

    } else {
        // ---------------- openings + barrier reset ----------------
        __shared__ int scnt[256];
        scnt[tid] = d_cnt[tid];
        __syncthreads();
        for (int st = 128; st > 0; st >>= 1) {
            if (tid < st) scnt[tid] += scnt[tid + st];
            __syncthreads();
        }
        if (tid == 0) {
            o_open[0] = (float)scnt[0] * (1.f / (float)GATE_ELEMS);
            d_done = 0;                  // reset grid barrier for next replay
        }
    }
}

// ---------------------------------------------------------------------------
extern "C" void kernel_launch(void* const* d_in, const int* in_sizes, int n_in,
                              void* d_out, int out_size)
{
    const float* x      = (const float*)d_in[0];
    const float* h_last = (const float*)d_in[1];
    const float* w_gx   = (const float*)d_in[2];
    const float* w_gh   = (const float*)d_in[3];
    const float* b_g    = (const float*)d_in[4];
    const float* w_rx   = (const float*)d_in[5];
    const float* w_rh   = (const float*)d_in[6];
    const float* b_r    = (const float*)d_in[7];
    const float* w_px   = (const float*)d_in[8];
    const float* w_ph   = (const float*)d_in[9];
    const float* b_p    = (const float*)d_in[10];
    const float* w_ox   = (const float*)d_in[11];
    const float* w_oh   = (const float*)d_in[12];
    const float* b_o    = (const float*)d_in[13];
    const float* e_w_gx = (const float*)d_in[14];
    const float* e_w_gh = (const float*)d_in[15];
    const float* e_b_g  = (const float*)d_in[16];
    const float* e_w_rx = (const float*)d_in[17];
    const float* e_w_rh = (const float*)d_in[18];
    const float* e_b_r  = (const float*)d_in[19];

    float* out    = (float*)d_out;
    float* o_out  = out;                  // (128,512)
    float* o_h    = out + 65536;          // (128,512)
    float* o_egx  = out + 131072;         // (128,512,512)
    float* o_egh  = out + 33685504;       // (128,512,512)
    float* o_ebg  = out + 67239936;       // (128,512)
    float* o_erx  = out + 67305472;       // (128,512,512)
    float* o_erh  = out + 100859904;      // (128,512,512)
    float* o_ebr  = out + 134414336;      // (128,512)
    float* o_open = out + 134479872;      // scalar

    // Launch 1: g/r GEMM (split-K=16, 128x64 tiles, 256 CTAs, 2/SM)
    //           + in-kernel gate epilogue after the grid barrier
    k_gemm1<<<dim3(16, NSPLIT), 256>>>(x, h_last, w_gx, w_gh, w_rx, w_rh,
                                       b_g, b_r, e_b_g, e_b_r,
                                       o_h, o_ebg, o_ebr);

    // Launch 2: parallel P/O GEMM blocks + trace streamer + openings
    k_fused<<<TRACE_BASE + TRACE_BLOCKS + 1, 256>>>(
        x, h_last, w_px, w_ph, w_ox, w_oh, b_p, b_o,
        e_w_gx, e_w_gh, e_w_rx, e_w_rh,
        o_egx, o_egh, o_erx, o_erh,
        o_out, o_open);
}